// round 12
// baseline (speedup 1.0000x reference)
#include <cuda_runtime.h>
#include <math.h>

#define BS      256
#define HID     1024
#define ACT     16
#define MEM_DIM 512
#define NUM_MEM 1024
#define NSPLIT  64
#define NCHUNK  (NUM_MEM / NSPLIT)   // 16 memory rows per block
#define MBATCH  8

// GEMM split-K factors (R8-proven configuration)
#define KS_EA 2
#define KS_G1 4
#define KS_OT 2

// Output layout (tuple concat): read_v | other_v | M_new | alpha
#define OUT_READV 0
#define OUT_OTHER (BS * MEM_DIM)                       // 131072
#define OUT_MNEW  (2 * BS * MEM_DIM)                   // 262144
#define OUT_ALPHA (2 * BS * MEM_DIM + BS * NUM_MEM * MEM_DIM)  // 134479872

// ---------------- scratch (device globals; no allocation allowed) ----------
__device__ __align__(16) float g_rvpart[NSPLIT * BS * MEM_DIM];      // 32 MB
__device__ __align__(16) float g_part_ea[KS_EA * BS * 2 * MEM_DIM];  // 2 MB
__device__ __align__(16) float g_part_g1[KS_G1 * BS * MEM_DIM];      // 2 MB
__device__ __align__(16) float g_part_ot[KS_OT * BS * MEM_DIM];      // 1 MB

__device__ __forceinline__ float leakyf(float x) { return x > 0.f ? x : 0.2f * x; }
__device__ __forceinline__ float sigmoidf_(float x) { return 1.f / (1.f + expf(-x)); }

// ---------------- split-K double-buffered SGEMM partials -------------------
__global__ void gemm_part_kernel(const float* __restrict__ H,
                                 const float* __restrict__ W, int ldw, int wc0,
                                 float* __restrict__ part, int ncols, int kper) {
    const int n0 = blockIdx.x * 64;
    const int m0 = blockIdx.y * 64;
    const int kbase = blockIdx.z * kper;

    __shared__ __align__(16) float As[2][16][64];
    __shared__ __align__(16) float Bs[2][16][64];

    int tid = threadIdx.x;
    int tx = tid & 15, ty = tid >> 4;
    int a_m = tid >> 2;
    int a_k = (tid & 3) * 4;
    int b_k = tid >> 4;
    int b_n = (tid & 15) * 4;

    const float* Aptr = H + (size_t)(m0 + a_m) * HID + kbase + a_k;
    const float* Bptr = W + (size_t)(kbase + b_k) * ldw + wc0 + n0 + b_n;

    float4 av = *(const float4*)Aptr;
    float4 bvv = *(const float4*)Bptr;
    As[0][a_k + 0][a_m] = av.x;
    As[0][a_k + 1][a_m] = av.y;
    As[0][a_k + 2][a_m] = av.z;
    As[0][a_k + 3][a_m] = av.w;
    *(float4*)&Bs[0][b_k][b_n] = bvv;
    __syncthreads();

    float acc[4][4] = {};
    int buf = 0;
    const int iters = kper / 16;

    for (int it = 1; it < iters; it++) {
        av = *(const float4*)(Aptr + it * 16);
        bvv = *(const float4*)(Bptr + (size_t)it * 16 * ldw);

        #pragma unroll
        for (int k = 0; k < 16; k++) {
            float4 a4 = *(const float4*)&As[buf][k][ty * 4];
            float4 b4 = *(const float4*)&Bs[buf][k][tx * 4];
            float ar[4] = {a4.x, a4.y, a4.z, a4.w};
            float br[4] = {b4.x, b4.y, b4.z, b4.w};
            #pragma unroll
            for (int i = 0; i < 4; i++)
                #pragma unroll
                for (int j = 0; j < 4; j++)
                    acc[i][j] = fmaf(ar[i], br[j], acc[i][j]);
        }

        int nb = buf ^ 1;
        As[nb][a_k + 0][a_m] = av.x;
        As[nb][a_k + 1][a_m] = av.y;
        As[nb][a_k + 2][a_m] = av.z;
        As[nb][a_k + 3][a_m] = av.w;
        *(float4*)&Bs[nb][b_k][b_n] = bvv;
        __syncthreads();
        buf = nb;
    }

    #pragma unroll
    for (int k = 0; k < 16; k++) {
        float4 a4 = *(const float4*)&As[buf][k][ty * 4];
        float4 b4 = *(const float4*)&Bs[buf][k][tx * 4];
        float ar[4] = {a4.x, a4.y, a4.z, a4.w};
        float br[4] = {b4.x, b4.y, b4.z, b4.w};
        #pragma unroll
        for (int i = 0; i < 4; i++)
            #pragma unroll
            for (int j = 0; j < 4; j++)
                acc[i][j] = fmaf(ar[i], br[j], acc[i][j]);
    }

    #pragma unroll
    for (int i = 0; i < 4; i++) {
        float4 o = make_float4(acc[i][0], acc[i][1], acc[i][2], acc[i][3]);
        *(float4*)&part[((size_t)blockIdx.z * BS + m0 + ty * 4 + i) * ncols +
                        n0 + tx * 4] = o;
    }
}

// ---------------- epilogue: other_v -> d_out -------------------------------
__global__ void epi_other_kernel(const float* __restrict__ bv,
                                 float* __restrict__ out_other) {
    int idx = blockIdx.x * 256 + threadIdx.x;  // 32768 float4
    int row = idx >> 7;
    int c = (idx & 127) * 4;
    float4 s = ((const float4*)g_part_ot)[(0 * BS + row) * 128 + (idx & 127)];
    #pragma unroll
    for (int ks = 1; ks < KS_OT; ks++) {
        float4 p = ((const float4*)g_part_ot)[((size_t)ks * BS + row) * 128 + (idx & 127)];
        s.x += p.x; s.y += p.y; s.z += p.z; s.w += p.w;
    }
    float4 b4 = *(const float4*)(bv + 2 * MEM_DIM + c);
    s.x += b4.x; s.y += b4.y; s.z += b4.z; s.w += b4.w;
    *(float4*)&out_other[row * MEM_DIM + c] = s;
}

// ---------------- fused: kernel-net + gate + 3x3 conv + blend -> alpha -----
__global__ void conv_fused_kernel(const float* __restrict__ A,
                                  const float* __restrict__ Wk1,
                                  const float* __restrict__ bk1,
                                  const float* __restrict__ Wk2,
                                  const float* __restrict__ bk2,
                                  const float* __restrict__ bg1,
                                  const float* __restrict__ Wg2,
                                  const float* __restrict__ bg2,
                                  const float* __restrict__ prev_alpha,
                                  float* __restrict__ alpha_out) {
    int b = blockIdx.x;
    int tid = threadIdx.x;  // 256
    int lane = tid & 31, wid = tid >> 5;  // 8 warps

    __shared__ float sa[ACT], sna[ACT];
    __shared__ float spart[8][9], spartb[8][9], sgp[8];
    __shared__ float kk[9];
    __shared__ float sgate;
    __shared__ int sm_flag;
    __shared__ float t[34][34];

    if (tid < ACT) {
        float v = A[b * ACT + tid];
        sa[tid] = v;
        sna[tid] = v;
    }
    __syncthreads();
    if (tid == 0) {
        int am = 0;
        float best = sa[0];
        for (int i = 1; i < ACT; i++)
            if (sa[i] > best) { best = sa[i]; am = i; }
        int m = (am == 0);
        sm_flag = m;
        if (m) { sna[0] = 0.f; sna[1] = 1.f; }
    }
    {
        float* tf = &t[0][0];
        for (int i = tid; i < 34 * 34; i += 256) tf[i] = 0.f;
    }
    __syncthreads();

    float p[9] = {}, pb[9] = {};
    #pragma unroll
    for (int half = 0; half < 2; half++) {
        int j = tid + half * 256;
        float x = bk1[j], xb = x;
        #pragma unroll
        for (int i = 0; i < ACT; i++) {
            float w = Wk1[i * MEM_DIM + j];
            x = fmaf(sa[i], w, x);
            xb = fmaf(sna[i], w, xb);
        }
        x = leakyf(x);
        xb = leakyf(xb);
        #pragma unroll
        for (int tt = 0; tt < 9; tt++) {
            float w = Wk2[j * 9 + tt];
            p[tt] = fmaf(x, w, p[tt]);
            pb[tt] = fmaf(xb, w, pb[tt]);
        }
    }
    float gv = 0.f;
    #pragma unroll
    for (int half = 0; half < 2; half++) {
        int c = tid + half * 256;
        float v = bg1[c];
        #pragma unroll
        for (int ks = 0; ks < KS_G1; ks++)
            v += g_part_g1[((size_t)ks * BS + b) * MEM_DIM + c];
        gv = fmaf(leakyf(v), Wg2[c], gv);
    }

    #pragma unroll
    for (int tt = 0; tt < 9; tt++) {
        #pragma unroll
        for (int o = 16; o > 0; o >>= 1) {
            p[tt] += __shfl_down_sync(0xffffffffu, p[tt], o);
            pb[tt] += __shfl_down_sync(0xffffffffu, pb[tt], o);
        }
    }
    #pragma unroll
    for (int o = 16; o > 0; o >>= 1) gv += __shfl_down_sync(0xffffffffu, gv, o);
    if (lane == 0) {
        #pragma unroll
        for (int tt = 0; tt < 9; tt++) { spart[wid][tt] = p[tt]; spartb[wid][tt] = pb[tt]; }
        sgp[wid] = gv;
    }
    __syncthreads();

    if (tid == 64) {
        float s = bg2[0];
        #pragma unroll
        for (int w = 0; w < 8; w++) s += sgp[w];
        sgate = sigmoidf_(s);
    }
    if (tid == 0) {
        float kkr[9], kkbr[9];
        #pragma unroll
        for (int tt = 0; tt < 9; tt++) {
            float s = bk2[tt], sb = bk2[tt];
            #pragma unroll
            for (int w = 0; w < 8; w++) { s += spart[w][tt]; sb += spartb[w][tt]; }
            kkr[tt] = s; kkbr[tt] = sb;
        }
        int m = sm_flag;
        float v[9];
        #pragma unroll
        for (int i = 0; i < 9; i++) v[i] = m ? kkbr[8 - i] : kkr[i];
        float mx = v[0];
        #pragma unroll
        for (int i = 1; i < 9; i++) mx = fmaxf(mx, v[i]);
        float sum = 0.f;
        #pragma unroll
        for (int i = 0; i < 9; i++) { v[i] = expf(v[i] - mx); sum += v[i]; }
        float inv = 1.f / sum;
        #pragma unroll
        for (int i = 0; i < 9; i++) kk[i] = v[i] * inv;
    }
    __syncthreads();

    for (int i = tid; i < 1024; i += 256)
        t[1 + (i >> 5)][1 + (i & 31)] = prev_alpha[b * 1024 + i];
    __syncthreads();
    float g = sgate;
    for (int i = tid; i < 1024; i += 256) {
        int y = i >> 5, x = i & 31;
        float s = 0.f;
        #pragma unroll
        for (int ky = 0; ky < 3; ky++)
            #pragma unroll
            for (int kx = 0; kx < 3; kx++)
                s = fmaf(t[y + ky][x + kx], kk[ky * 3 + kx], s);
        float pa = t[1 + y][1 + x];
        alpha_out[b * 1024 + i] = s * g + pa * (1.f - g);
    }
}

// ---------------- M update (inline erase/add epilogue) + partial read_v ----
__global__ void mupdate_kernel(const float* __restrict__ M,
                               const float* __restrict__ alpha,
                               const float* __restrict__ bv,
                               float* __restrict__ mnew) {
    int b = blockIdx.y;
    int c = blockIdx.x;
    int d4 = threadIdx.x;        // 0..127
    __shared__ float sal[NCHUNK];
    if (d4 < NCHUNK) sal[d4] = alpha[b * NUM_MEM + c * NCHUNK + d4];

    // reconstruct erase/add for (b, d4) from KS partials (+bias)
    float4 e = *(const float4*)(bv + d4 * 4);
    float4 v = *(const float4*)(bv + MEM_DIM + d4 * 4);
    #pragma unroll
    for (int ks = 0; ks < KS_EA; ks++) {
        float4 pe = ((const float4*)g_part_ea)[((size_t)ks * BS + b) * 256 + d4];
        float4 pv = ((const float4*)g_part_ea)[((size_t)ks * BS + b) * 256 + 128 + d4];
        e.x += pe.x; e.y += pe.y; e.z += pe.z; e.w += pe.w;
        v.x += pv.x; v.y += pv.y; v.z += pv.z; v.w += pv.w;
    }
    e.x = sigmoidf_(e.x); e.y = sigmoidf_(e.y);
    e.z = sigmoidf_(e.z); e.w = sigmoidf_(e.w);
    __syncthreads();

    size_t base = (size_t)b * (NUM_MEM * 128) + (size_t)c * (NCHUNK * 128);
    const float4* Mb = (const float4*)M + base;
    float4* Ob = (float4*)mnew + base;
    float4 rv = make_float4(0.f, 0.f, 0.f, 0.f);

    // explicit batched load phase then compute+store phase
    for (int n0 = 0; n0 < NCHUNK; n0 += MBATCH) {
        float4 m[MBATCH];
        #pragma unroll
        for (int i = 0; i < MBATCH; i++)
            m[i] = __ldcs(&Mb[(n0 + i) * 128 + d4]);
        #pragma unroll
        for (int i = 0; i < MBATCH; i++) {
            float a = sal[n0 + i];
            float4 mn;
            mn.x = fmaf(a, fmaf(-m[i].x, e.x, v.x), m[i].x);
            mn.y = fmaf(a, fmaf(-m[i].y, e.y, v.y), m[i].y);
            mn.z = fmaf(a, fmaf(-m[i].z, e.z, v.z), m[i].z);
            mn.w = fmaf(a, fmaf(-m[i].w, e.w, v.w), m[i].w);
            rv.x = fmaf(a, mn.x, rv.x);
            rv.y = fmaf(a, mn.y, rv.y);
            rv.z = fmaf(a, mn.z, rv.z);
            rv.w = fmaf(a, mn.w, rv.w);
            __stcs(&Ob[(n0 + i) * 128 + d4], mn);
        }
    }
    ((float4*)g_rvpart)[((size_t)c * BS + b) * 128 + d4] = rv;
}

// ---------------- reduce read_v partials (separate kernel: coherent) -------
__global__ void rvreduce_kernel(float* __restrict__ readv) {
    int b = blockIdx.x;
    int d4 = threadIdx.x;  // 128
    float4 s = make_float4(0.f, 0.f, 0.f, 0.f);
    #pragma unroll
    for (int c = 0; c < NSPLIT; c++) {
        float4 p = ((const float4*)g_rvpart)[((size_t)c * BS + b) * 128 + d4];
        s.x += p.x; s.y += p.y; s.z += p.z; s.w += p.w;
    }
    ((float4*)readv)[b * 128 + d4] = s;
}

// ---------------- launch ----------------------------------------------------
extern "C" void kernel_launch(void* const* d_in, const int* in_sizes, int n_in,
                              void* d_out, int out_size) {
    const float* h          = (const float*)d_in[0];
    const float* a          = (const float*)d_in[1];
    const float* prev_alpha = (const float*)d_in[3];
    const float* M          = (const float*)d_in[4];
    const float* Wv         = (const float*)d_in[5];
    const float* bv         = (const float*)d_in[6];
    const float* Wk1        = (const float*)d_in[7];
    const float* bk1        = (const float*)d_in[8];
    const float* Wk2        = (const float*)d_in[9];
    const float* bk2        = (const float*)d_in[10];
    const float* Wg1        = (const float*)d_in[11];
    const float* bg1        = (const float*)d_in[12];
    const float* Wg2        = (const float*)d_in[13];
    const float* bg2        = (const float*)d_in[14];

    float* out = (float*)d_out;
    float* out_readv = out + OUT_READV;
    float* out_other = out + OUT_OTHER;
    float* out_mnew  = out + OUT_MNEW;
    float* out_alpha = out + OUT_ALPHA;

    static cudaStream_t s1 = 0;
    static cudaEvent_t evFork = 0, evJoin = 0, evJoin2 = 0;
    static float *p_ea = 0, *p_g1 = 0, *p_ot = 0;
    static int tried = 0, ok = 0;
    if (!tried) {
        tried = 1;
        ok = (cudaStreamCreateWithFlags(&s1, cudaStreamNonBlocking) == cudaSuccess) &&
             (cudaEventCreateWithFlags(&evFork, cudaEventDisableTiming) == cudaSuccess) &&
             (cudaEventCreateWithFlags(&evJoin, cudaEventDisableTiming) == cudaSuccess) &&
             (cudaEventCreateWithFlags(&evJoin2, cudaEventDisableTiming) == cudaSuccess) &&
             (cudaGetSymbolAddress((void**)&p_ea, g_part_ea) == cudaSuccess) &&
             (cudaGetSymbolAddress((void**)&p_g1, g_part_g1) == cudaSuccess) &&
             (cudaGetSymbolAddress((void**)&p_ot, g_part_ot) == cudaSuccess);
    }
    if (!ok) return;

    // fork
    cudaEventRecord(evFork, 0);
    cudaStreamWaitEvent(s1, evFork, 0);

    // s1: erase/add slab partials (Wv cols 0..1024), KS=2 -> 128 blocks
    gemm_part_kernel<<<dim3(16, 4, KS_EA), 256, 0, s1>>>(
        h, Wv, 3 * MEM_DIM, 0, p_ea, 2 * MEM_DIM, HID / KS_EA);
    cudaEventRecord(evJoin, s1);
    // s1: other_v slab (overlaps conv/mupdate)
    gemm_part_kernel<<<dim3(8, 4, KS_OT), 256, 0, s1>>>(
        h, Wv, 3 * MEM_DIM, 2 * MEM_DIM, p_ot, MEM_DIM, HID / KS_OT);
    epi_other_kernel<<<128, 256, 0, s1>>>(bv, out_other);
    cudaEventRecord(evJoin2, s1);

    // default: g1 gemm partials (KS=4, 128 blocks) -> fused conv -> mupdate
    gemm_part_kernel<<<dim3(8, 4, KS_G1), 256>>>(
        h, Wg1, MEM_DIM, 0, p_g1, MEM_DIM, HID / KS_G1);
    conv_fused_kernel<<<BS, 256>>>(a, Wk1, bk1, Wk2, bk2, bg1, Wg2, bg2,
                                   prev_alpha, out_alpha);

    cudaStreamWaitEvent(0, evJoin, 0);
    mupdate_kernel<<<dim3(NSPLIT, BS), 128>>>(M, out_alpha, bv, out_mnew);
    rvreduce_kernel<<<BS, 128>>>(out_readv);
    cudaStreamWaitEvent(0, evJoin2, 0);
}

// round 13
// speedup vs baseline: 1.0228x; 1.0228x over previous
#include <cuda_runtime.h>
#include <math.h>

#define BS      256
#define HID     1024
#define ACT     16
#define MEM_DIM 512
#define NUM_MEM 1024
#define NSPLIT  32
#define NCHUNK  (NUM_MEM / NSPLIT)   // 32 memory rows per block
#define MBATCH  8

// GEMM split-K factors (R8-proven configuration)
#define KS_EA 2
#define KS_G1 4
#define KS_OT 2

// Output layout (tuple concat): read_v | other_v | M_new | alpha
#define OUT_READV 0
#define OUT_OTHER (BS * MEM_DIM)                       // 131072
#define OUT_MNEW  (2 * BS * MEM_DIM)                   // 262144
#define OUT_ALPHA (2 * BS * MEM_DIM + BS * NUM_MEM * MEM_DIM)  // 134479872

// ---------------- scratch (device globals; no allocation allowed) ----------
__device__ __align__(16) float g_rvpart[NSPLIT * BS * MEM_DIM];      // 16 MB
__device__ __align__(16) float g_part_ea[KS_EA * BS * 2 * MEM_DIM];  // 2 MB
__device__ __align__(16) float g_part_g1[KS_G1 * BS * MEM_DIM];      // 2 MB
__device__ __align__(16) float g_part_ot[KS_OT * BS * MEM_DIM];      // 1 MB

__device__ __forceinline__ float leakyf(float x) { return x > 0.f ? x : 0.2f * x; }
__device__ __forceinline__ float sigmoidf_(float x) { return 1.f / (1.f + expf(-x)); }

// ---------------- split-K double-buffered SGEMM partials -------------------
__global__ void gemm_part_kernel(const float* __restrict__ H,
                                 const float* __restrict__ W, int ldw, int wc0,
                                 float* __restrict__ part, int ncols, int kper) {
    const int n0 = blockIdx.x * 64;
    const int m0 = blockIdx.y * 64;
    const int kbase = blockIdx.z * kper;

    __shared__ __align__(16) float As[2][16][64];
    __shared__ __align__(16) float Bs[2][16][64];

    int tid = threadIdx.x;
    int tx = tid & 15, ty = tid >> 4;
    int a_m = tid >> 2;
    int a_k = (tid & 3) * 4;
    int b_k = tid >> 4;
    int b_n = (tid & 15) * 4;

    const float* Aptr = H + (size_t)(m0 + a_m) * HID + kbase + a_k;
    const float* Bptr = W + (size_t)(kbase + b_k) * ldw + wc0 + n0 + b_n;

    float4 av = *(const float4*)Aptr;
    float4 bvv = *(const float4*)Bptr;
    As[0][a_k + 0][a_m] = av.x;
    As[0][a_k + 1][a_m] = av.y;
    As[0][a_k + 2][a_m] = av.z;
    As[0][a_k + 3][a_m] = av.w;
    *(float4*)&Bs[0][b_k][b_n] = bvv;
    __syncthreads();

    float acc[4][4] = {};
    int buf = 0;
    const int iters = kper / 16;

    for (int it = 1; it < iters; it++) {
        av = *(const float4*)(Aptr + it * 16);
        bvv = *(const float4*)(Bptr + (size_t)it * 16 * ldw);

        #pragma unroll
        for (int k = 0; k < 16; k++) {
            float4 a4 = *(const float4*)&As[buf][k][ty * 4];
            float4 b4 = *(const float4*)&Bs[buf][k][tx * 4];
            float ar[4] = {a4.x, a4.y, a4.z, a4.w};
            float br[4] = {b4.x, b4.y, b4.z, b4.w};
            #pragma unroll
            for (int i = 0; i < 4; i++)
                #pragma unroll
                for (int j = 0; j < 4; j++)
                    acc[i][j] = fmaf(ar[i], br[j], acc[i][j]);
        }

        int nb = buf ^ 1;
        As[nb][a_k + 0][a_m] = av.x;
        As[nb][a_k + 1][a_m] = av.y;
        As[nb][a_k + 2][a_m] = av.z;
        As[nb][a_k + 3][a_m] = av.w;
        *(float4*)&Bs[nb][b_k][b_n] = bvv;
        __syncthreads();
        buf = nb;
    }

    #pragma unroll
    for (int k = 0; k < 16; k++) {
        float4 a4 = *(const float4*)&As[buf][k][ty * 4];
        float4 b4 = *(const float4*)&Bs[buf][k][tx * 4];
        float ar[4] = {a4.x, a4.y, a4.z, a4.w};
        float br[4] = {b4.x, b4.y, b4.z, b4.w};
        #pragma unroll
        for (int i = 0; i < 4; i++)
            #pragma unroll
            for (int j = 0; j < 4; j++)
                acc[i][j] = fmaf(ar[i], br[j], acc[i][j]);
    }

    #pragma unroll
    for (int i = 0; i < 4; i++) {
        float4 o = make_float4(acc[i][0], acc[i][1], acc[i][2], acc[i][3]);
        *(float4*)&part[((size_t)blockIdx.z * BS + m0 + ty * 4 + i) * ncols +
                        n0 + tx * 4] = o;
    }
}

// ---------------- epilogue: other_v -> d_out -------------------------------
__global__ void epi_other_kernel(const float* __restrict__ bv,
                                 float* __restrict__ out_other) {
    int idx = blockIdx.x * 256 + threadIdx.x;  // 32768 float4
    int row = idx >> 7;
    int c = (idx & 127) * 4;
    float4 s = ((const float4*)g_part_ot)[(0 * BS + row) * 128 + (idx & 127)];
    #pragma unroll
    for (int ks = 1; ks < KS_OT; ks++) {
        float4 p = ((const float4*)g_part_ot)[((size_t)ks * BS + row) * 128 + (idx & 127)];
        s.x += p.x; s.y += p.y; s.z += p.z; s.w += p.w;
    }
    float4 b4 = *(const float4*)(bv + 2 * MEM_DIM + c);
    s.x += b4.x; s.y += b4.y; s.z += b4.z; s.w += b4.w;
    *(float4*)&out_other[row * MEM_DIM + c] = s;
}

// ---------------- fused: kernel-net + gate + 3x3 conv + blend -> alpha -----
__global__ void conv_fused_kernel(const float* __restrict__ A,
                                  const float* __restrict__ Wk1,
                                  const float* __restrict__ bk1,
                                  const float* __restrict__ Wk2,
                                  const float* __restrict__ bk2,
                                  const float* __restrict__ bg1,
                                  const float* __restrict__ Wg2,
                                  const float* __restrict__ bg2,
                                  const float* __restrict__ prev_alpha,
                                  float* __restrict__ alpha_out) {
    int b = blockIdx.x;
    int tid = threadIdx.x;  // 256
    int lane = tid & 31, wid = tid >> 5;  // 8 warps

    __shared__ float sa[ACT], sna[ACT];
    __shared__ float spart[8][9], spartb[8][9], sgp[8];
    __shared__ float kk[9];
    __shared__ float sgate;
    __shared__ int sm_flag;
    __shared__ float t[34][34];

    if (tid < ACT) {
        float v = A[b * ACT + tid];
        sa[tid] = v;
        sna[tid] = v;
    }
    __syncthreads();
    if (tid == 0) {
        int am = 0;
        float best = sa[0];
        for (int i = 1; i < ACT; i++)
            if (sa[i] > best) { best = sa[i]; am = i; }
        int m = (am == 0);
        sm_flag = m;
        if (m) { sna[0] = 0.f; sna[1] = 1.f; }
    }
    {
        float* tf = &t[0][0];
        for (int i = tid; i < 34 * 34; i += 256) tf[i] = 0.f;
    }
    __syncthreads();

    float p[9] = {}, pb[9] = {};
    #pragma unroll
    for (int half = 0; half < 2; half++) {
        int j = tid + half * 256;
        float x = bk1[j], xb = x;
        #pragma unroll
        for (int i = 0; i < ACT; i++) {
            float w = Wk1[i * MEM_DIM + j];
            x = fmaf(sa[i], w, x);
            xb = fmaf(sna[i], w, xb);
        }
        x = leakyf(x);
        xb = leakyf(xb);
        #pragma unroll
        for (int tt = 0; tt < 9; tt++) {
            float w = Wk2[j * 9 + tt];
            p[tt] = fmaf(x, w, p[tt]);
            pb[tt] = fmaf(xb, w, pb[tt]);
        }
    }
    float gv = 0.f;
    #pragma unroll
    for (int half = 0; half < 2; half++) {
        int c = tid + half * 256;
        float v = bg1[c];
        #pragma unroll
        for (int ks = 0; ks < KS_G1; ks++)
            v += g_part_g1[((size_t)ks * BS + b) * MEM_DIM + c];
        gv = fmaf(leakyf(v), Wg2[c], gv);
    }

    #pragma unroll
    for (int tt = 0; tt < 9; tt++) {
        #pragma unroll
        for (int o = 16; o > 0; o >>= 1) {
            p[tt] += __shfl_down_sync(0xffffffffu, p[tt], o);
            pb[tt] += __shfl_down_sync(0xffffffffu, pb[tt], o);
        }
    }
    #pragma unroll
    for (int o = 16; o > 0; o >>= 1) gv += __shfl_down_sync(0xffffffffu, gv, o);
    if (lane == 0) {
        #pragma unroll
        for (int tt = 0; tt < 9; tt++) { spart[wid][tt] = p[tt]; spartb[wid][tt] = pb[tt]; }
        sgp[wid] = gv;
    }
    __syncthreads();

    if (tid == 64) {
        float s = bg2[0];
        #pragma unroll
        for (int w = 0; w < 8; w++) s += sgp[w];
        sgate = sigmoidf_(s);
    }
    if (tid == 0) {
        float kkr[9], kkbr[9];
        #pragma unroll
        for (int tt = 0; tt < 9; tt++) {
            float s = bk2[tt], sb = bk2[tt];
            #pragma unroll
            for (int w = 0; w < 8; w++) { s += spart[w][tt]; sb += spartb[w][tt]; }
            kkr[tt] = s; kkbr[tt] = sb;
        }
        int m = sm_flag;
        float v[9];
        #pragma unroll
        for (int i = 0; i < 9; i++) v[i] = m ? kkbr[8 - i] : kkr[i];
        float mx = v[0];
        #pragma unroll
        for (int i = 1; i < 9; i++) mx = fmaxf(mx, v[i]);
        float sum = 0.f;
        #pragma unroll
        for (int i = 0; i < 9; i++) { v[i] = expf(v[i] - mx); sum += v[i]; }
        float inv = 1.f / sum;
        #pragma unroll
        for (int i = 0; i < 9; i++) kk[i] = v[i] * inv;
    }
    __syncthreads();

    for (int i = tid; i < 1024; i += 256)
        t[1 + (i >> 5)][1 + (i & 31)] = prev_alpha[b * 1024 + i];
    __syncthreads();
    float g = sgate;
    for (int i = tid; i < 1024; i += 256) {
        int y = i >> 5, x = i & 31;
        float s = 0.f;
        #pragma unroll
        for (int ky = 0; ky < 3; ky++)
            #pragma unroll
            for (int kx = 0; kx < 3; kx++)
                s = fmaf(t[y + ky][x + kx], kk[ky * 3 + kx], s);
        float pa = t[1 + y][1 + x];
        alpha_out[b * 1024 + i] = s * g + pa * (1.f - g);
    }
}

// ---------------- M update (inline erase/add epilogue) + partial read_v ----
__global__ void mupdate_kernel(const float* __restrict__ M,
                               const float* __restrict__ alpha,
                               const float* __restrict__ bv,
                               float* __restrict__ mnew) {
    int b = blockIdx.y;
    int c = blockIdx.x;
    int d4 = threadIdx.x;        // 0..127
    __shared__ float sal[NCHUNK];
    if (d4 < NCHUNK) sal[d4] = alpha[b * NUM_MEM + c * NCHUNK + d4];

    // reconstruct erase/add for (b, d4) from KS partials (+bias)
    float4 e = *(const float4*)(bv + d4 * 4);
    float4 v = *(const float4*)(bv + MEM_DIM + d4 * 4);
    #pragma unroll
    for (int ks = 0; ks < KS_EA; ks++) {
        float4 pe = ((const float4*)g_part_ea)[((size_t)ks * BS + b) * 256 + d4];
        float4 pv = ((const float4*)g_part_ea)[((size_t)ks * BS + b) * 256 + 128 + d4];
        e.x += pe.x; e.y += pe.y; e.z += pe.z; e.w += pe.w;
        v.x += pv.x; v.y += pv.y; v.z += pv.z; v.w += pv.w;
    }
    e.x = sigmoidf_(e.x); e.y = sigmoidf_(e.y);
    e.z = sigmoidf_(e.z); e.w = sigmoidf_(e.w);
    __syncthreads();

    size_t base = (size_t)b * (NUM_MEM * 128) + (size_t)c * (NCHUNK * 128);
    const float4* Mb = (const float4*)M + base;
    float4* Ob = (float4*)mnew + base;
    float4 rv = make_float4(0.f, 0.f, 0.f, 0.f);

    // explicit batched load phase then compute+store phase
    for (int n0 = 0; n0 < NCHUNK; n0 += MBATCH) {
        float4 m[MBATCH];
        #pragma unroll
        for (int i = 0; i < MBATCH; i++)
            m[i] = __ldcs(&Mb[(n0 + i) * 128 + d4]);
        #pragma unroll
        for (int i = 0; i < MBATCH; i++) {
            float a = sal[n0 + i];
            float4 mn;
            mn.x = fmaf(a, fmaf(-m[i].x, e.x, v.x), m[i].x);
            mn.y = fmaf(a, fmaf(-m[i].y, e.y, v.y), m[i].y);
            mn.z = fmaf(a, fmaf(-m[i].z, e.z, v.z), m[i].z);
            mn.w = fmaf(a, fmaf(-m[i].w, e.w, v.w), m[i].w);
            rv.x = fmaf(a, mn.x, rv.x);
            rv.y = fmaf(a, mn.y, rv.y);
            rv.z = fmaf(a, mn.z, rv.z);
            rv.w = fmaf(a, mn.w, rv.w);
            __stcs(&Ob[(n0 + i) * 128 + d4], mn);
        }
    }
    ((float4*)g_rvpart)[((size_t)c * BS + b) * 128 + d4] = rv;
}

// ---------------- reduce read_v partials (separate kernel: coherent) -------
__global__ void rvreduce_kernel(float* __restrict__ readv) {
    int b = blockIdx.x;
    int d4 = threadIdx.x;  // 128
    float4 s = make_float4(0.f, 0.f, 0.f, 0.f);
    #pragma unroll
    for (int c = 0; c < NSPLIT; c++) {
        float4 p = ((const float4*)g_rvpart)[((size_t)c * BS + b) * 128 + d4];
        s.x += p.x; s.y += p.y; s.z += p.z; s.w += p.w;
    }
    ((float4*)readv)[b * 128 + d4] = s;
}

// ---------------- launch ----------------------------------------------------
extern "C" void kernel_launch(void* const* d_in, const int* in_sizes, int n_in,
                              void* d_out, int out_size) {
    const float* h          = (const float*)d_in[0];
    const float* a          = (const float*)d_in[1];
    const float* prev_alpha = (const float*)d_in[3];
    const float* M          = (const float*)d_in[4];
    const float* Wv         = (const float*)d_in[5];
    const float* bv         = (const float*)d_in[6];
    const float* Wk1        = (const float*)d_in[7];
    const float* bk1        = (const float*)d_in[8];
    const float* Wk2        = (const float*)d_in[9];
    const float* bk2        = (const float*)d_in[10];
    const float* Wg1        = (const float*)d_in[11];
    const float* bg1        = (const float*)d_in[12];
    const float* Wg2        = (const float*)d_in[13];
    const float* bg2        = (const float*)d_in[14];

    float* out = (float*)d_out;
    float* out_readv = out + OUT_READV;
    float* out_other = out + OUT_OTHER;
    float* out_mnew  = out + OUT_MNEW;
    float* out_alpha = out + OUT_ALPHA;

    static cudaStream_t s1 = 0;
    static cudaEvent_t evFork = 0, evJoin = 0, evJoin2 = 0;
    static float *p_ea = 0, *p_g1 = 0, *p_ot = 0;
    static int tried = 0, ok = 0;
    if (!tried) {
        tried = 1;
        ok = (cudaStreamCreateWithFlags(&s1, cudaStreamNonBlocking) == cudaSuccess) &&
             (cudaEventCreateWithFlags(&evFork, cudaEventDisableTiming) == cudaSuccess) &&
             (cudaEventCreateWithFlags(&evJoin, cudaEventDisableTiming) == cudaSuccess) &&
             (cudaEventCreateWithFlags(&evJoin2, cudaEventDisableTiming) == cudaSuccess) &&
             (cudaGetSymbolAddress((void**)&p_ea, g_part_ea) == cudaSuccess) &&
             (cudaGetSymbolAddress((void**)&p_g1, g_part_g1) == cudaSuccess) &&
             (cudaGetSymbolAddress((void**)&p_ot, g_part_ot) == cudaSuccess);
    }
    if (!ok) return;

    // fork
    cudaEventRecord(evFork, 0);
    cudaStreamWaitEvent(s1, evFork, 0);

    // s1: erase/add slab partials (Wv cols 0..1024), KS=2 -> 128 blocks
    gemm_part_kernel<<<dim3(16, 4, KS_EA), 256, 0, s1>>>(
        h, Wv, 3 * MEM_DIM, 0, p_ea, 2 * MEM_DIM, HID / KS_EA);
    cudaEventRecord(evJoin, s1);
    // s1: other_v slab (overlaps conv/mupdate)
    gemm_part_kernel<<<dim3(8, 4, KS_OT), 256, 0, s1>>>(
        h, Wv, 3 * MEM_DIM, 2 * MEM_DIM, p_ot, MEM_DIM, HID / KS_OT);
    epi_other_kernel<<<128, 256, 0, s1>>>(bv, out_other);
    cudaEventRecord(evJoin2, s1);

    // default: g1 gemm partials (KS=4, 128 blocks) -> fused conv -> mupdate
    gemm_part_kernel<<<dim3(8, 4, KS_G1), 256>>>(
        h, Wg1, MEM_DIM, 0, p_g1, MEM_DIM, HID / KS_G1);
    conv_fused_kernel<<<BS, 256>>>(a, Wk1, bk1, Wk2, bk2, bg1, Wg2, bg2,
                                   prev_alpha, out_alpha);

    cudaStreamWaitEvent(0, evJoin, 0);
    mupdate_kernel<<<dim3(NSPLIT, BS), 128>>>(M, out_alpha, bv, out_mnew);
    rvreduce_kernel<<<BS, 128>>>(out_readv);
    cudaStreamWaitEvent(0, evJoin2, 0);
}

// round 14
// speedup vs baseline: 1.0400x; 1.0168x over previous
#include <cuda_runtime.h>
#include <math.h>

#define BS      256
#define HID     1024
#define ACT     16
#define MEM_DIM 512
#define NUM_MEM 1024
#define NSPLIT  32
#define NCHUNK  (NUM_MEM / NSPLIT)   // 32 memory rows per block
#define MBATCH  16

// GEMM split-K factors (R8-proven configuration)
#define KS_EA 2
#define KS_G1 4
#define KS_OT 2

// Output layout (tuple concat): read_v | other_v | M_new | alpha
#define OUT_READV 0
#define OUT_OTHER (BS * MEM_DIM)                       // 131072
#define OUT_MNEW  (2 * BS * MEM_DIM)                   // 262144
#define OUT_ALPHA (2 * BS * MEM_DIM + BS * NUM_MEM * MEM_DIM)  // 134479872

// ---------------- scratch (device globals; no allocation allowed) ----------
__device__ __align__(16) float g_rvpart[NSPLIT * BS * MEM_DIM];      // 16 MB
__device__ __align__(16) float g_part_ea[KS_EA * BS * 2 * MEM_DIM];  // 2 MB
__device__ __align__(16) float g_part_g1[KS_G1 * BS * MEM_DIM];      // 2 MB
__device__ __align__(16) float g_part_ot[KS_OT * BS * MEM_DIM];      // 1 MB

__device__ __forceinline__ float leakyf(float x) { return x > 0.f ? x : 0.2f * x; }
__device__ __forceinline__ float sigmoidf_(float x) { return 1.f / (1.f + expf(-x)); }

// ---------------- split-K double-buffered SGEMM partials -------------------
__global__ void gemm_part_kernel(const float* __restrict__ H,
                                 const float* __restrict__ W, int ldw, int wc0,
                                 float* __restrict__ part, int ncols, int kper) {
    const int n0 = blockIdx.x * 64;
    const int m0 = blockIdx.y * 64;
    const int kbase = blockIdx.z * kper;

    __shared__ __align__(16) float As[2][16][64];
    __shared__ __align__(16) float Bs[2][16][64];

    int tid = threadIdx.x;
    int tx = tid & 15, ty = tid >> 4;
    int a_m = tid >> 2;
    int a_k = (tid & 3) * 4;
    int b_k = tid >> 4;
    int b_n = (tid & 15) * 4;

    const float* Aptr = H + (size_t)(m0 + a_m) * HID + kbase + a_k;
    const float* Bptr = W + (size_t)(kbase + b_k) * ldw + wc0 + n0 + b_n;

    float4 av = *(const float4*)Aptr;
    float4 bvv = *(const float4*)Bptr;
    As[0][a_k + 0][a_m] = av.x;
    As[0][a_k + 1][a_m] = av.y;
    As[0][a_k + 2][a_m] = av.z;
    As[0][a_k + 3][a_m] = av.w;
    *(float4*)&Bs[0][b_k][b_n] = bvv;
    __syncthreads();

    float acc[4][4] = {};
    int buf = 0;
    const int iters = kper / 16;

    for (int it = 1; it < iters; it++) {
        av = *(const float4*)(Aptr + it * 16);
        bvv = *(const float4*)(Bptr + (size_t)it * 16 * ldw);

        #pragma unroll
        for (int k = 0; k < 16; k++) {
            float4 a4 = *(const float4*)&As[buf][k][ty * 4];
            float4 b4 = *(const float4*)&Bs[buf][k][tx * 4];
            float ar[4] = {a4.x, a4.y, a4.z, a4.w};
            float br[4] = {b4.x, b4.y, b4.z, b4.w};
            #pragma unroll
            for (int i = 0; i < 4; i++)
                #pragma unroll
                for (int j = 0; j < 4; j++)
                    acc[i][j] = fmaf(ar[i], br[j], acc[i][j]);
        }

        int nb = buf ^ 1;
        As[nb][a_k + 0][a_m] = av.x;
        As[nb][a_k + 1][a_m] = av.y;
        As[nb][a_k + 2][a_m] = av.z;
        As[nb][a_k + 3][a_m] = av.w;
        *(float4*)&Bs[nb][b_k][b_n] = bvv;
        __syncthreads();
        buf = nb;
    }

    #pragma unroll
    for (int k = 0; k < 16; k++) {
        float4 a4 = *(const float4*)&As[buf][k][ty * 4];
        float4 b4 = *(const float4*)&Bs[buf][k][tx * 4];
        float ar[4] = {a4.x, a4.y, a4.z, a4.w};
        float br[4] = {b4.x, b4.y, b4.z, b4.w};
        #pragma unroll
        for (int i = 0; i < 4; i++)
            #pragma unroll
            for (int j = 0; j < 4; j++)
                acc[i][j] = fmaf(ar[i], br[j], acc[i][j]);
    }

    #pragma unroll
    for (int i = 0; i < 4; i++) {
        float4 o = make_float4(acc[i][0], acc[i][1], acc[i][2], acc[i][3]);
        *(float4*)&part[((size_t)blockIdx.z * BS + m0 + ty * 4 + i) * ncols +
                        n0 + tx * 4] = o;
    }
}

// ---------------- epilogue: other_v -> d_out -------------------------------
__global__ void epi_other_kernel(const float* __restrict__ bv,
                                 float* __restrict__ out_other) {
    int idx = blockIdx.x * 256 + threadIdx.x;  // 32768 float4
    int row = idx >> 7;
    int c = (idx & 127) * 4;
    float4 s = ((const float4*)g_part_ot)[(0 * BS + row) * 128 + (idx & 127)];
    #pragma unroll
    for (int ks = 1; ks < KS_OT; ks++) {
        float4 p = ((const float4*)g_part_ot)[((size_t)ks * BS + row) * 128 + (idx & 127)];
        s.x += p.x; s.y += p.y; s.z += p.z; s.w += p.w;
    }
    float4 b4 = *(const float4*)(bv + 2 * MEM_DIM + c);
    s.x += b4.x; s.y += b4.y; s.z += b4.z; s.w += b4.w;
    *(float4*)&out_other[row * MEM_DIM + c] = s;
}

// ---------------- fused: kernel-net + gate + 3x3 conv + blend -> alpha -----
__global__ void conv_fused_kernel(const float* __restrict__ A,
                                  const float* __restrict__ Wk1,
                                  const float* __restrict__ bk1,
                                  const float* __restrict__ Wk2,
                                  const float* __restrict__ bk2,
                                  const float* __restrict__ bg1,
                                  const float* __restrict__ Wg2,
                                  const float* __restrict__ bg2,
                                  const float* __restrict__ prev_alpha,
                                  float* __restrict__ alpha_out) {
    int b = blockIdx.x;
    int tid = threadIdx.x;  // 256
    int lane = tid & 31, wid = tid >> 5;  // 8 warps

    __shared__ float sa[ACT], sna[ACT];
    __shared__ float spart[8][9], spartb[8][9], sgp[8];
    __shared__ float kk[9];
    __shared__ float sgate;
    __shared__ int sm_flag;
    __shared__ float t[34][34];

    if (tid < ACT) {
        float v = A[b * ACT + tid];
        sa[tid] = v;
        sna[tid] = v;
    }
    __syncthreads();
    if (tid == 0) {
        int am = 0;
        float best = sa[0];
        for (int i = 1; i < ACT; i++)
            if (sa[i] > best) { best = sa[i]; am = i; }
        int m = (am == 0);
        sm_flag = m;
        if (m) { sna[0] = 0.f; sna[1] = 1.f; }
    }
    {
        float* tf = &t[0][0];
        for (int i = tid; i < 34 * 34; i += 256) tf[i] = 0.f;
    }
    __syncthreads();

    float p[9] = {}, pb[9] = {};
    #pragma unroll
    for (int half = 0; half < 2; half++) {
        int j = tid + half * 256;
        float x = bk1[j], xb = x;
        #pragma unroll
        for (int i = 0; i < ACT; i++) {
            float w = Wk1[i * MEM_DIM + j];
            x = fmaf(sa[i], w, x);
            xb = fmaf(sna[i], w, xb);
        }
        x = leakyf(x);
        xb = leakyf(xb);
        #pragma unroll
        for (int tt = 0; tt < 9; tt++) {
            float w = Wk2[j * 9 + tt];
            p[tt] = fmaf(x, w, p[tt]);
            pb[tt] = fmaf(xb, w, pb[tt]);
        }
    }
    float gv = 0.f;
    #pragma unroll
    for (int half = 0; half < 2; half++) {
        int c = tid + half * 256;
        float v = bg1[c];
        #pragma unroll
        for (int ks = 0; ks < KS_G1; ks++)
            v += g_part_g1[((size_t)ks * BS + b) * MEM_DIM + c];
        gv = fmaf(leakyf(v), Wg2[c], gv);
    }

    #pragma unroll
    for (int tt = 0; tt < 9; tt++) {
        #pragma unroll
        for (int o = 16; o > 0; o >>= 1) {
            p[tt] += __shfl_down_sync(0xffffffffu, p[tt], o);
            pb[tt] += __shfl_down_sync(0xffffffffu, pb[tt], o);
        }
    }
    #pragma unroll
    for (int o = 16; o > 0; o >>= 1) gv += __shfl_down_sync(0xffffffffu, gv, o);
    if (lane == 0) {
        #pragma unroll
        for (int tt = 0; tt < 9; tt++) { spart[wid][tt] = p[tt]; spartb[wid][tt] = pb[tt]; }
        sgp[wid] = gv;
    }
    __syncthreads();

    if (tid == 64) {
        float s = bg2[0];
        #pragma unroll
        for (int w = 0; w < 8; w++) s += sgp[w];
        sgate = sigmoidf_(s);
    }
    if (tid == 0) {
        float kkr[9], kkbr[9];
        #pragma unroll
        for (int tt = 0; tt < 9; tt++) {
            float s = bk2[tt], sb = bk2[tt];
            #pragma unroll
            for (int w = 0; w < 8; w++) { s += spart[w][tt]; sb += spartb[w][tt]; }
            kkr[tt] = s; kkbr[tt] = sb;
        }
        int m = sm_flag;
        float v[9];
        #pragma unroll
        for (int i = 0; i < 9; i++) v[i] = m ? kkbr[8 - i] : kkr[i];
        float mx = v[0];
        #pragma unroll
        for (int i = 1; i < 9; i++) mx = fmaxf(mx, v[i]);
        float sum = 0.f;
        #pragma unroll
        for (int i = 0; i < 9; i++) { v[i] = expf(v[i] - mx); sum += v[i]; }
        float inv = 1.f / sum;
        #pragma unroll
        for (int i = 0; i < 9; i++) kk[i] = v[i] * inv;
    }
    __syncthreads();

    for (int i = tid; i < 1024; i += 256)
        t[1 + (i >> 5)][1 + (i & 31)] = prev_alpha[b * 1024 + i];
    __syncthreads();
    float g = sgate;
    for (int i = tid; i < 1024; i += 256) {
        int y = i >> 5, x = i & 31;
        float s = 0.f;
        #pragma unroll
        for (int ky = 0; ky < 3; ky++)
            #pragma unroll
            for (int kx = 0; kx < 3; kx++)
                s = fmaf(t[y + ky][x + kx], kk[ky * 3 + kx], s);
        float pa = t[1 + y][1 + x];
        alpha_out[b * 1024 + i] = s * g + pa * (1.f - g);
    }
}

// ---------------- M update (inline erase/add epilogue) + partial read_v ----
__global__ void mupdate_kernel(const float* __restrict__ M,
                               const float* __restrict__ alpha,
                               const float* __restrict__ bv,
                               float* __restrict__ mnew) {
    int b = blockIdx.y;
    int c = blockIdx.x;
    int d4 = threadIdx.x;        // 0..127
    __shared__ float sal[NCHUNK];
    if (d4 < NCHUNK) sal[d4] = alpha[b * NUM_MEM + c * NCHUNK + d4];

    // reconstruct erase/add for (b, d4) from KS partials (+bias)
    float4 e = *(const float4*)(bv + d4 * 4);
    float4 v = *(const float4*)(bv + MEM_DIM + d4 * 4);
    #pragma unroll
    for (int ks = 0; ks < KS_EA; ks++) {
        float4 pe = ((const float4*)g_part_ea)[((size_t)ks * BS + b) * 256 + d4];
        float4 pv = ((const float4*)g_part_ea)[((size_t)ks * BS + b) * 256 + 128 + d4];
        e.x += pe.x; e.y += pe.y; e.z += pe.z; e.w += pe.w;
        v.x += pv.x; v.y += pv.y; v.z += pv.z; v.w += pv.w;
    }
    e.x = sigmoidf_(e.x); e.y = sigmoidf_(e.y);
    e.z = sigmoidf_(e.z); e.w = sigmoidf_(e.w);
    __syncthreads();

    size_t base = (size_t)b * (NUM_MEM * 128) + (size_t)c * (NCHUNK * 128);
    const float4* Mb = (const float4*)M + base;
    float4* Ob = (float4*)mnew + base;
    float4 rv = make_float4(0.f, 0.f, 0.f, 0.f);

    // explicit batched load phase then compute+store phase (deep read bursts)
    for (int n0 = 0; n0 < NCHUNK; n0 += MBATCH) {
        float4 m[MBATCH];
        #pragma unroll
        for (int i = 0; i < MBATCH; i++)
            m[i] = __ldcs(&Mb[(n0 + i) * 128 + d4]);
        #pragma unroll
        for (int i = 0; i < MBATCH; i++) {
            float a = sal[n0 + i];
            float4 mn;
            mn.x = fmaf(a, fmaf(-m[i].x, e.x, v.x), m[i].x);
            mn.y = fmaf(a, fmaf(-m[i].y, e.y, v.y), m[i].y);
            mn.z = fmaf(a, fmaf(-m[i].z, e.z, v.z), m[i].z);
            mn.w = fmaf(a, fmaf(-m[i].w, e.w, v.w), m[i].w);
            rv.x = fmaf(a, mn.x, rv.x);
            rv.y = fmaf(a, mn.y, rv.y);
            rv.z = fmaf(a, mn.z, rv.z);
            rv.w = fmaf(a, mn.w, rv.w);
            __stcs(&Ob[(n0 + i) * 128 + d4], mn);
        }
    }
    ((float4*)g_rvpart)[((size_t)c * BS + b) * 128 + d4] = rv;
}

// ---------------- reduce read_v partials (separate kernel: coherent) -------
__global__ void rvreduce_kernel(float* __restrict__ readv) {
    int b = blockIdx.x;
    int d4 = threadIdx.x;  // 128
    float4 s = make_float4(0.f, 0.f, 0.f, 0.f);
    #pragma unroll
    for (int c = 0; c < NSPLIT; c++) {
        float4 p = ((const float4*)g_rvpart)[((size_t)c * BS + b) * 128 + d4];
        s.x += p.x; s.y += p.y; s.z += p.z; s.w += p.w;
    }
    ((float4*)readv)[b * 128 + d4] = s;
}

// ---------------- launch ----------------------------------------------------
extern "C" void kernel_launch(void* const* d_in, const int* in_sizes, int n_in,
                              void* d_out, int out_size) {
    const float* h          = (const float*)d_in[0];
    const float* a          = (const float*)d_in[1];
    const float* prev_alpha = (const float*)d_in[3];
    const float* M          = (const float*)d_in[4];
    const float* Wv         = (const float*)d_in[5];
    const float* bv         = (const float*)d_in[6];
    const float* Wk1        = (const float*)d_in[7];
    const float* bk1        = (const float*)d_in[8];
    const float* Wk2        = (const float*)d_in[9];
    const float* bk2        = (const float*)d_in[10];
    const float* Wg1        = (const float*)d_in[11];
    const float* bg1        = (const float*)d_in[12];
    const float* Wg2        = (const float*)d_in[13];
    const float* bg2        = (const float*)d_in[14];

    float* out = (float*)d_out;
    float* out_readv = out + OUT_READV;
    float* out_other = out + OUT_OTHER;
    float* out_mnew  = out + OUT_MNEW;
    float* out_alpha = out + OUT_ALPHA;

    static cudaStream_t s1 = 0;
    static cudaEvent_t evFork = 0, evJoin = 0, evJoin2 = 0;
    static float *p_ea = 0, *p_g1 = 0, *p_ot = 0;
    static int tried = 0, ok = 0;
    if (!tried) {
        tried = 1;
        ok = (cudaStreamCreateWithFlags(&s1, cudaStreamNonBlocking) == cudaSuccess) &&
             (cudaEventCreateWithFlags(&evFork, cudaEventDisableTiming) == cudaSuccess) &&
             (cudaEventCreateWithFlags(&evJoin, cudaEventDisableTiming) == cudaSuccess) &&
             (cudaEventCreateWithFlags(&evJoin2, cudaEventDisableTiming) == cudaSuccess) &&
             (cudaGetSymbolAddress((void**)&p_ea, g_part_ea) == cudaSuccess) &&
             (cudaGetSymbolAddress((void**)&p_g1, g_part_g1) == cudaSuccess) &&
             (cudaGetSymbolAddress((void**)&p_ot, g_part_ot) == cudaSuccess);
    }
    if (!ok) return;

    // fork
    cudaEventRecord(evFork, 0);
    cudaStreamWaitEvent(s1, evFork, 0);

    // s1: erase/add slab partials (Wv cols 0..1024), KS=2 -> 128 blocks
    gemm_part_kernel<<<dim3(16, 4, KS_EA), 256, 0, s1>>>(
        h, Wv, 3 * MEM_DIM, 0, p_ea, 2 * MEM_DIM, HID / KS_EA);
    cudaEventRecord(evJoin, s1);
    // s1: other_v slab (overlaps conv/mupdate)
    gemm_part_kernel<<<dim3(8, 4, KS_OT), 256, 0, s1>>>(
        h, Wv, 3 * MEM_DIM, 2 * MEM_DIM, p_ot, MEM_DIM, HID / KS_OT);
    epi_other_kernel<<<128, 256, 0, s1>>>(bv, out_other);
    cudaEventRecord(evJoin2, s1);

    // default: g1 gemm partials (KS=4, 128 blocks) -> fused conv -> mupdate
    gemm_part_kernel<<<dim3(8, 4, KS_G1), 256>>>(
        h, Wg1, MEM_DIM, 0, p_g1, MEM_DIM, HID / KS_G1);
    conv_fused_kernel<<<BS, 256>>>(a, Wk1, bk1, Wk2, bk2, bg1, Wg2, bg2,
                                   prev_alpha, out_alpha);

    cudaStreamWaitEvent(0, evJoin, 0);
    mupdate_kernel<<<dim3(NSPLIT, BS), 128>>>(M, out_alpha, bv, out_mnew);
    rvreduce_kernel<<<BS, 128>>>(out_readv);
    cudaStreamWaitEvent(0, evJoin2, 0);
}

// round 15
// speedup vs baseline: 1.0478x; 1.0075x over previous
#include <cuda_runtime.h>
#include <math.h>

#define BS      256
#define HID     1024
#define ACT     16
#define MEM_DIM 512
#define NUM_MEM 1024
#define NSPLIT  32
#define NCHUNK  (NUM_MEM / NSPLIT)   // 32 memory rows per block
#define MBATCH  32                    // full-chunk single read burst

// GEMM split-K factors (R8-proven configuration)
#define KS_EA 2
#define KS_G1 4
#define KS_OT 2

// Output layout (tuple concat): read_v | other_v | M_new | alpha
#define OUT_READV 0
#define OUT_OTHER (BS * MEM_DIM)                       // 131072
#define OUT_MNEW  (2 * BS * MEM_DIM)                   // 262144
#define OUT_ALPHA (2 * BS * MEM_DIM + BS * NUM_MEM * MEM_DIM)  // 134479872

// ---------------- scratch (device globals; no allocation allowed) ----------
__device__ __align__(16) float g_rvpart[NSPLIT * BS * MEM_DIM];      // 16 MB
__device__ __align__(16) float g_part_ea[KS_EA * BS * 2 * MEM_DIM];  // 2 MB
__device__ __align__(16) float g_part_g1[KS_G1 * BS * MEM_DIM];      // 2 MB
__device__ __align__(16) float g_part_ot[KS_OT * BS * MEM_DIM];      // 1 MB

__device__ __forceinline__ float leakyf(float x) { return x > 0.f ? x : 0.2f * x; }
__device__ __forceinline__ float sigmoidf_(float x) { return 1.f / (1.f + expf(-x)); }

// ---------------- split-K double-buffered SGEMM partials -------------------
__global__ void gemm_part_kernel(const float* __restrict__ H,
                                 const float* __restrict__ W, int ldw, int wc0,
                                 float* __restrict__ part, int ncols, int kper) {
    const int n0 = blockIdx.x * 64;
    const int m0 = blockIdx.y * 64;
    const int kbase = blockIdx.z * kper;

    __shared__ __align__(16) float As[2][16][64];
    __shared__ __align__(16) float Bs[2][16][64];

    int tid = threadIdx.x;
    int tx = tid & 15, ty = tid >> 4;
    int a_m = tid >> 2;
    int a_k = (tid & 3) * 4;
    int b_k = tid >> 4;
    int b_n = (tid & 15) * 4;

    const float* Aptr = H + (size_t)(m0 + a_m) * HID + kbase + a_k;
    const float* Bptr = W + (size_t)(kbase + b_k) * ldw + wc0 + n0 + b_n;

    float4 av = *(const float4*)Aptr;
    float4 bvv = *(const float4*)Bptr;
    As[0][a_k + 0][a_m] = av.x;
    As[0][a_k + 1][a_m] = av.y;
    As[0][a_k + 2][a_m] = av.z;
    As[0][a_k + 3][a_m] = av.w;
    *(float4*)&Bs[0][b_k][b_n] = bvv;
    __syncthreads();

    float acc[4][4] = {};
    int buf = 0;
    const int iters = kper / 16;

    for (int it = 1; it < iters; it++) {
        av = *(const float4*)(Aptr + it * 16);
        bvv = *(const float4*)(Bptr + (size_t)it * 16 * ldw);

        #pragma unroll
        for (int k = 0; k < 16; k++) {
            float4 a4 = *(const float4*)&As[buf][k][ty * 4];
            float4 b4 = *(const float4*)&Bs[buf][k][tx * 4];
            float ar[4] = {a4.x, a4.y, a4.z, a4.w};
            float br[4] = {b4.x, b4.y, b4.z, b4.w};
            #pragma unroll
            for (int i = 0; i < 4; i++)
                #pragma unroll
                for (int j = 0; j < 4; j++)
                    acc[i][j] = fmaf(ar[i], br[j], acc[i][j]);
        }

        int nb = buf ^ 1;
        As[nb][a_k + 0][a_m] = av.x;
        As[nb][a_k + 1][a_m] = av.y;
        As[nb][a_k + 2][a_m] = av.z;
        As[nb][a_k + 3][a_m] = av.w;
        *(float4*)&Bs[nb][b_k][b_n] = bvv;
        __syncthreads();
        buf = nb;
    }

    #pragma unroll
    for (int k = 0; k < 16; k++) {
        float4 a4 = *(const float4*)&As[buf][k][ty * 4];
        float4 b4 = *(const float4*)&Bs[buf][k][tx * 4];
        float ar[4] = {a4.x, a4.y, a4.z, a4.w};
        float br[4] = {b4.x, b4.y, b4.z, b4.w};
        #pragma unroll
        for (int i = 0; i < 4; i++)
            #pragma unroll
            for (int j = 0; j < 4; j++)
                acc[i][j] = fmaf(ar[i], br[j], acc[i][j]);
    }

    #pragma unroll
    for (int i = 0; i < 4; i++) {
        float4 o = make_float4(acc[i][0], acc[i][1], acc[i][2], acc[i][3]);
        *(float4*)&part[((size_t)blockIdx.z * BS + m0 + ty * 4 + i) * ncols +
                        n0 + tx * 4] = o;
    }
}

// ---------------- epilogue: other_v -> d_out -------------------------------
__global__ void epi_other_kernel(const float* __restrict__ bv,
                                 float* __restrict__ out_other) {
    int idx = blockIdx.x * 256 + threadIdx.x;  // 32768 float4
    int row = idx >> 7;
    int c = (idx & 127) * 4;
    float4 s = ((const float4*)g_part_ot)[(0 * BS + row) * 128 + (idx & 127)];
    #pragma unroll
    for (int ks = 1; ks < KS_OT; ks++) {
        float4 p = ((const float4*)g_part_ot)[((size_t)ks * BS + row) * 128 + (idx & 127)];
        s.x += p.x; s.y += p.y; s.z += p.z; s.w += p.w;
    }
    float4 b4 = *(const float4*)(bv + 2 * MEM_DIM + c);
    s.x += b4.x; s.y += b4.y; s.z += b4.z; s.w += b4.w;
    *(float4*)&out_other[row * MEM_DIM + c] = s;
}

// ---------------- fused: kernel-net + gate + 3x3 conv + blend -> alpha -----
__global__ void conv_fused_kernel(const float* __restrict__ A,
                                  const float* __restrict__ Wk1,
                                  const float* __restrict__ bk1,
                                  const float* __restrict__ Wk2,
                                  const float* __restrict__ bk2,
                                  const float* __restrict__ bg1,
                                  const float* __restrict__ Wg2,
                                  const float* __restrict__ bg2,
                                  const float* __restrict__ prev_alpha,
                                  float* __restrict__ alpha_out) {
    int b = blockIdx.x;
    int tid = threadIdx.x;  // 256
    int lane = tid & 31, wid = tid >> 5;  // 8 warps

    __shared__ float sa[ACT], sna[ACT];
    __shared__ float spart[8][9], spartb[8][9], sgp[8];
    __shared__ float kk[9];
    __shared__ float sgate;
    __shared__ int sm_flag;
    __shared__ float t[34][34];

    if (tid < ACT) {
        float v = A[b * ACT + tid];
        sa[tid] = v;
        sna[tid] = v;
    }
    __syncthreads();
    if (tid == 0) {
        int am = 0;
        float best = sa[0];
        for (int i = 1; i < ACT; i++)
            if (sa[i] > best) { best = sa[i]; am = i; }
        int m = (am == 0);
        sm_flag = m;
        if (m) { sna[0] = 0.f; sna[1] = 1.f; }
    }
    {
        float* tf = &t[0][0];
        for (int i = tid; i < 34 * 34; i += 256) tf[i] = 0.f;
    }
    __syncthreads();

    float p[9] = {}, pb[9] = {};
    #pragma unroll
    for (int half = 0; half < 2; half++) {
        int j = tid + half * 256;
        float x = bk1[j], xb = x;
        #pragma unroll
        for (int i = 0; i < ACT; i++) {
            float w = Wk1[i * MEM_DIM + j];
            x = fmaf(sa[i], w, x);
            xb = fmaf(sna[i], w, xb);
        }
        x = leakyf(x);
        xb = leakyf(xb);
        #pragma unroll
        for (int tt = 0; tt < 9; tt++) {
            float w = Wk2[j * 9 + tt];
            p[tt] = fmaf(x, w, p[tt]);
            pb[tt] = fmaf(xb, w, pb[tt]);
        }
    }
    float gv = 0.f;
    #pragma unroll
    for (int half = 0; half < 2; half++) {
        int c = tid + half * 256;
        float v = bg1[c];
        #pragma unroll
        for (int ks = 0; ks < KS_G1; ks++)
            v += g_part_g1[((size_t)ks * BS + b) * MEM_DIM + c];
        gv = fmaf(leakyf(v), Wg2[c], gv);
    }

    #pragma unroll
    for (int tt = 0; tt < 9; tt++) {
        #pragma unroll
        for (int o = 16; o > 0; o >>= 1) {
            p[tt] += __shfl_down_sync(0xffffffffu, p[tt], o);
            pb[tt] += __shfl_down_sync(0xffffffffu, pb[tt], o);
        }
    }
    #pragma unroll
    for (int o = 16; o > 0; o >>= 1) gv += __shfl_down_sync(0xffffffffu, gv, o);
    if (lane == 0) {
        #pragma unroll
        for (int tt = 0; tt < 9; tt++) { spart[wid][tt] = p[tt]; spartb[wid][tt] = pb[tt]; }
        sgp[wid] = gv;
    }
    __syncthreads();

    if (tid == 64) {
        float s = bg2[0];
        #pragma unroll
        for (int w = 0; w < 8; w++) s += sgp[w];
        sgate = sigmoidf_(s);
    }
    if (tid == 0) {
        float kkr[9], kkbr[9];
        #pragma unroll
        for (int tt = 0; tt < 9; tt++) {
            float s = bk2[tt], sb = bk2[tt];
            #pragma unroll
            for (int w = 0; w < 8; w++) { s += spart[w][tt]; sb += spartb[w][tt]; }
            kkr[tt] = s; kkbr[tt] = sb;
        }
        int m = sm_flag;
        float v[9];
        #pragma unroll
        for (int i = 0; i < 9; i++) v[i] = m ? kkbr[8 - i] : kkr[i];
        float mx = v[0];
        #pragma unroll
        for (int i = 1; i < 9; i++) mx = fmaxf(mx, v[i]);
        float sum = 0.f;
        #pragma unroll
        for (int i = 0; i < 9; i++) { v[i] = expf(v[i] - mx); sum += v[i]; }
        float inv = 1.f / sum;
        #pragma unroll
        for (int i = 0; i < 9; i++) kk[i] = v[i] * inv;
    }
    __syncthreads();

    for (int i = tid; i < 1024; i += 256)
        t[1 + (i >> 5)][1 + (i & 31)] = prev_alpha[b * 1024 + i];
    __syncthreads();
    float g = sgate;
    for (int i = tid; i < 1024; i += 256) {
        int y = i >> 5, x = i & 31;
        float s = 0.f;
        #pragma unroll
        for (int ky = 0; ky < 3; ky++)
            #pragma unroll
            for (int kx = 0; kx < 3; kx++)
                s = fmaf(t[y + ky][x + kx], kk[ky * 3 + kx], s);
        float pa = t[1 + y][1 + x];
        alpha_out[b * 1024 + i] = s * g + pa * (1.f - g);
    }
}

// ---------------- M update (inline erase/add epilogue) + partial read_v ----
__global__ void mupdate_kernel(const float* __restrict__ M,
                               const float* __restrict__ alpha,
                               const float* __restrict__ bv,
                               float* __restrict__ mnew) {
    int b = blockIdx.y;
    int c = blockIdx.x;
    int d4 = threadIdx.x;        // 0..127
    __shared__ float sal[NCHUNK];
    if (d4 < NCHUNK) sal[d4] = alpha[b * NUM_MEM + c * NCHUNK + d4];

    // reconstruct erase/add for (b, d4) from KS partials (+bias)
    float4 e = *(const float4*)(bv + d4 * 4);
    float4 v = *(const float4*)(bv + MEM_DIM + d4 * 4);
    #pragma unroll
    for (int ks = 0; ks < KS_EA; ks++) {
        float4 pe = ((const float4*)g_part_ea)[((size_t)ks * BS + b) * 256 + d4];
        float4 pv = ((const float4*)g_part_ea)[((size_t)ks * BS + b) * 256 + 128 + d4];
        e.x += pe.x; e.y += pe.y; e.z += pe.z; e.w += pe.w;
        v.x += pv.x; v.y += pv.y; v.z += pv.z; v.w += pv.w;
    }
    e.x = sigmoidf_(e.x); e.y = sigmoidf_(e.y);
    e.z = sigmoidf_(e.z); e.w = sigmoidf_(e.w);
    __syncthreads();

    size_t base = (size_t)b * (NUM_MEM * 128) + (size_t)c * (NCHUNK * 128);
    const float4* Mb = (const float4*)M + base;
    float4* Ob = (float4*)mnew + base;
    float4 rv = make_float4(0.f, 0.f, 0.f, 0.f);

    // single full-chunk read burst, then compute+store burst (zero turnaround)
    float4 m[MBATCH];
    #pragma unroll
    for (int i = 0; i < MBATCH; i++)
        m[i] = __ldcs(&Mb[i * 128 + d4]);
    #pragma unroll
    for (int i = 0; i < MBATCH; i++) {
        float a = sal[i];
        float4 mn;
        mn.x = fmaf(a, fmaf(-m[i].x, e.x, v.x), m[i].x);
        mn.y = fmaf(a, fmaf(-m[i].y, e.y, v.y), m[i].y);
        mn.z = fmaf(a, fmaf(-m[i].z, e.z, v.z), m[i].z);
        mn.w = fmaf(a, fmaf(-m[i].w, e.w, v.w), m[i].w);
        rv.x = fmaf(a, mn.x, rv.x);
        rv.y = fmaf(a, mn.y, rv.y);
        rv.z = fmaf(a, mn.z, rv.z);
        rv.w = fmaf(a, mn.w, rv.w);
        __stcs(&Ob[i * 128 + d4], mn);
    }
    ((float4*)g_rvpart)[((size_t)c * BS + b) * 128 + d4] = rv;
}

// ---------------- reduce read_v partials (separate kernel: coherent) -------
__global__ void rvreduce_kernel(float* __restrict__ readv) {
    int b = blockIdx.x;
    int d4 = threadIdx.x;  // 128
    float4 s = make_float4(0.f, 0.f, 0.f, 0.f);
    #pragma unroll
    for (int c = 0; c < NSPLIT; c++) {
        float4 p = ((const float4*)g_rvpart)[((size_t)c * BS + b) * 128 + d4];
        s.x += p.x; s.y += p.y; s.z += p.z; s.w += p.w;
    }
    ((float4*)readv)[b * 128 + d4] = s;
}

// ---------------- launch ----------------------------------------------------
extern "C" void kernel_launch(void* const* d_in, const int* in_sizes, int n_in,
                              void* d_out, int out_size) {
    const float* h          = (const float*)d_in[0];
    const float* a          = (const float*)d_in[1];
    const float* prev_alpha = (const float*)d_in[3];
    const float* M          = (const float*)d_in[4];
    const float* Wv         = (const float*)d_in[5];
    const float* bv         = (const float*)d_in[6];
    const float* Wk1        = (const float*)d_in[7];
    const float* bk1        = (const float*)d_in[8];
    const float* Wk2        = (const float*)d_in[9];
    const float* bk2        = (const float*)d_in[10];
    const float* Wg1        = (const float*)d_in[11];
    const float* bg1        = (const float*)d_in[12];
    const float* Wg2        = (const float*)d_in[13];
    const float* bg2        = (const float*)d_in[14];

    float* out = (float*)d_out;
    float* out_readv = out + OUT_READV;
    float* out_other = out + OUT_OTHER;
    float* out_mnew  = out + OUT_MNEW;
    float* out_alpha = out + OUT_ALPHA;

    static cudaStream_t s1 = 0;
    static cudaEvent_t evFork = 0, evJoin = 0, evJoin2 = 0;
    static float *p_ea = 0, *p_g1 = 0, *p_ot = 0;
    static int tried = 0, ok = 0;
    if (!tried) {
        tried = 1;
        ok = (cudaStreamCreateWithFlags(&s1, cudaStreamNonBlocking) == cudaSuccess) &&
             (cudaEventCreateWithFlags(&evFork, cudaEventDisableTiming) == cudaSuccess) &&
             (cudaEventCreateWithFlags(&evJoin, cudaEventDisableTiming) == cudaSuccess) &&
             (cudaEventCreateWithFlags(&evJoin2, cudaEventDisableTiming) == cudaSuccess) &&
             (cudaGetSymbolAddress((void**)&p_ea, g_part_ea) == cudaSuccess) &&
             (cudaGetSymbolAddress((void**)&p_g1, g_part_g1) == cudaSuccess) &&
             (cudaGetSymbolAddress((void**)&p_ot, g_part_ot) == cudaSuccess);
    }
    if (!ok) return;

    // fork
    cudaEventRecord(evFork, 0);
    cudaStreamWaitEvent(s1, evFork, 0);

    // s1: erase/add slab partials (Wv cols 0..1024), KS=2 -> 128 blocks
    gemm_part_kernel<<<dim3(16, 4, KS_EA), 256, 0, s1>>>(
        h, Wv, 3 * MEM_DIM, 0, p_ea, 2 * MEM_DIM, HID / KS_EA);
    cudaEventRecord(evJoin, s1);
    // s1: other_v slab (overlaps conv/mupdate)
    gemm_part_kernel<<<dim3(8, 4, KS_OT), 256, 0, s1>>>(
        h, Wv, 3 * MEM_DIM, 2 * MEM_DIM, p_ot, MEM_DIM, HID / KS_OT);
    epi_other_kernel<<<128, 256, 0, s1>>>(bv, out_other);
    cudaEventRecord(evJoin2, s1);

    // default: g1 gemm partials (KS=4, 128 blocks) -> fused conv -> mupdate
    gemm_part_kernel<<<dim3(8, 4, KS_G1), 256>>>(
        h, Wg1, MEM_DIM, 0, p_g1, MEM_DIM, HID / KS_G1);
    conv_fused_kernel<<<BS, 256>>>(a, Wk1, bk1, Wk2, bk2, bg1, Wg2, bg2,
                                   prev_alpha, out_alpha);

    cudaStreamWaitEvent(0, evJoin, 0);
    mupdate_kernel<<<dim3(NSPLIT, BS), 128>>>(M, out_alpha, bv, out_mnew);
    rvreduce_kernel<<<BS, 128>>>(out_readv);
    cudaStreamWaitEvent(0, evJoin2, 0);
}

// round 16
// speedup vs baseline: 1.0495x; 1.0016x over previous
#include <cuda_runtime.h>
#include <math.h>

#define BS      256
#define HID     1024
#define ACT     16
#define MEM_DIM 512
#define NUM_MEM 1024
#define NSPLIT  32
#define NCHUNK  (NUM_MEM / NSPLIT)   // 32 memory rows = one alpha-image row
#define MBATCH  32                    // full-chunk single read burst

// GEMM split-K factors (proven configuration)
#define KS_EA 2
#define KS_G1 4
#define KS_OT 2

// Output layout (tuple concat): read_v | other_v | M_new | alpha
#define OUT_READV 0
#define OUT_OTHER (BS * MEM_DIM)                       // 131072
#define OUT_MNEW  (2 * BS * MEM_DIM)                   // 262144
#define OUT_ALPHA (2 * BS * MEM_DIM + BS * NUM_MEM * MEM_DIM)  // 134479872

// ---------------- scratch (device globals; no allocation allowed) ----------
__device__ __align__(16) float g_rvpart[NSPLIT * BS * MEM_DIM];      // 16 MB
__device__ __align__(16) float g_part_ea[KS_EA * BS * 2 * MEM_DIM];  // 2 MB
__device__ __align__(16) float g_part_g1[KS_G1 * BS * MEM_DIM];      // 2 MB
__device__ __align__(16) float g_part_ot[KS_OT * BS * MEM_DIM];      // 1 MB
__device__ __align__(16) float g_kern[BS * 9];
__device__ __align__(16) float g_gate[BS];

__device__ __forceinline__ float leakyf(float x) { return x > 0.f ? x : 0.2f * x; }
__device__ __forceinline__ float sigmoidf_(float x) { return 1.f / (1.f + expf(-x)); }

// ---------------- split-K double-buffered SGEMM partials -------------------
__global__ void gemm_part_kernel(const float* __restrict__ H,
                                 const float* __restrict__ W, int ldw, int wc0,
                                 float* __restrict__ part, int ncols, int kper) {
    const int n0 = blockIdx.x * 64;
    const int m0 = blockIdx.y * 64;
    const int kbase = blockIdx.z * kper;

    __shared__ __align__(16) float As[2][16][64];
    __shared__ __align__(16) float Bs[2][16][64];

    int tid = threadIdx.x;
    int tx = tid & 15, ty = tid >> 4;
    int a_m = tid >> 2;
    int a_k = (tid & 3) * 4;
    int b_k = tid >> 4;
    int b_n = (tid & 15) * 4;

    const float* Aptr = H + (size_t)(m0 + a_m) * HID + kbase + a_k;
    const float* Bptr = W + (size_t)(kbase + b_k) * ldw + wc0 + n0 + b_n;

    float4 av = *(const float4*)Aptr;
    float4 bvv = *(const float4*)Bptr;
    As[0][a_k + 0][a_m] = av.x;
    As[0][a_k + 1][a_m] = av.y;
    As[0][a_k + 2][a_m] = av.z;
    As[0][a_k + 3][a_m] = av.w;
    *(float4*)&Bs[0][b_k][b_n] = bvv;
    __syncthreads();

    float acc[4][4] = {};
    int buf = 0;
    const int iters = kper / 16;

    for (int it = 1; it < iters; it++) {
        av = *(const float4*)(Aptr + it * 16);
        bvv = *(const float4*)(Bptr + (size_t)it * 16 * ldw);

        #pragma unroll
        for (int k = 0; k < 16; k++) {
            float4 a4 = *(const float4*)&As[buf][k][ty * 4];
            float4 b4 = *(const float4*)&Bs[buf][k][tx * 4];
            float ar[4] = {a4.x, a4.y, a4.z, a4.w};
            float br[4] = {b4.x, b4.y, b4.z, b4.w};
            #pragma unroll
            for (int i = 0; i < 4; i++)
                #pragma unroll
                for (int j = 0; j < 4; j++)
                    acc[i][j] = fmaf(ar[i], br[j], acc[i][j]);
        }

        int nb = buf ^ 1;
        As[nb][a_k + 0][a_m] = av.x;
        As[nb][a_k + 1][a_m] = av.y;
        As[nb][a_k + 2][a_m] = av.z;
        As[nb][a_k + 3][a_m] = av.w;
        *(float4*)&Bs[nb][b_k][b_n] = bvv;
        __syncthreads();
        buf = nb;
    }

    #pragma unroll
    for (int k = 0; k < 16; k++) {
        float4 a4 = *(const float4*)&As[buf][k][ty * 4];
        float4 b4 = *(const float4*)&Bs[buf][k][tx * 4];
        float ar[4] = {a4.x, a4.y, a4.z, a4.w};
        float br[4] = {b4.x, b4.y, b4.z, b4.w};
        #pragma unroll
        for (int i = 0; i < 4; i++)
            #pragma unroll
            for (int j = 0; j < 4; j++)
                acc[i][j] = fmaf(ar[i], br[j], acc[i][j]);
    }

    #pragma unroll
    for (int i = 0; i < 4; i++) {
        float4 o = make_float4(acc[i][0], acc[i][1], acc[i][2], acc[i][3]);
        *(float4*)&part[((size_t)blockIdx.z * BS + m0 + ty * 4 + i) * ncols +
                        n0 + tx * 4] = o;
    }
}

// ---------------- epilogue: other_v -> d_out -------------------------------
__global__ void epi_other_kernel(const float* __restrict__ bv,
                                 float* __restrict__ out_other) {
    int idx = blockIdx.x * 256 + threadIdx.x;  // 32768 float4
    int row = idx >> 7;
    int c = (idx & 127) * 4;
    float4 s = ((const float4*)g_part_ot)[(0 * BS + row) * 128 + (idx & 127)];
    #pragma unroll
    for (int ks = 1; ks < KS_OT; ks++) {
        float4 p = ((const float4*)g_part_ot)[((size_t)ks * BS + row) * 128 + (idx & 127)];
        s.x += p.x; s.y += p.y; s.z += p.z; s.w += p.w;
    }
    float4 b4 = *(const float4*)(bv + 2 * MEM_DIM + c);
    s.x += b4.x; s.y += b4.y; s.z += b4.z; s.w += b4.w;
    *(float4*)&out_other[row * MEM_DIM + c] = s;
}

// ---------------- prep: kernel-net + flip + softmax + gate -----------------
// one block per batch row, 256 threads. Writes g_kern[b*9..], g_gate[b].
__global__ void prep_kernel(const float* __restrict__ A,
                            const float* __restrict__ Wk1,
                            const float* __restrict__ bk1,
                            const float* __restrict__ Wk2,
                            const float* __restrict__ bk2,
                            const float* __restrict__ bg1,
                            const float* __restrict__ Wg2,
                            const float* __restrict__ bg2) {
    int b = blockIdx.x;
    int tid = threadIdx.x;  // 256
    int lane = tid & 31, wid = tid >> 5;  // 8 warps

    __shared__ float sa[ACT], sna[ACT];
    __shared__ float spart[8][9], spartb[8][9], sgp[8];
    __shared__ int sm_flag;

    if (tid < ACT) {
        float v = A[b * ACT + tid];
        sa[tid] = v;
        sna[tid] = v;
    }
    __syncthreads();
    if (tid == 0) {
        int am = 0;
        float best = sa[0];
        for (int i = 1; i < ACT; i++)
            if (sa[i] > best) { best = sa[i]; am = i; }
        int m = (am == 0);
        sm_flag = m;
        if (m) { sna[0] = 0.f; sna[1] = 1.f; }
    }
    __syncthreads();

    float p[9] = {}, pb[9] = {};
    #pragma unroll
    for (int half = 0; half < 2; half++) {
        int j = tid + half * 256;
        float x = bk1[j], xb = x;
        #pragma unroll
        for (int i = 0; i < ACT; i++) {
            float w = Wk1[i * MEM_DIM + j];
            x = fmaf(sa[i], w, x);
            xb = fmaf(sna[i], w, xb);
        }
        x = leakyf(x);
        xb = leakyf(xb);
        #pragma unroll
        for (int tt = 0; tt < 9; tt++) {
            float w = Wk2[j * 9 + tt];
            p[tt] = fmaf(x, w, p[tt]);
            pb[tt] = fmaf(xb, w, pb[tt]);
        }
    }
    float gv = 0.f;
    #pragma unroll
    for (int half = 0; half < 2; half++) {
        int c = tid + half * 256;
        float v = bg1[c];
        #pragma unroll
        for (int ks = 0; ks < KS_G1; ks++)
            v += g_part_g1[((size_t)ks * BS + b) * MEM_DIM + c];
        gv = fmaf(leakyf(v), Wg2[c], gv);
    }

    #pragma unroll
    for (int tt = 0; tt < 9; tt++) {
        #pragma unroll
        for (int o = 16; o > 0; o >>= 1) {
            p[tt] += __shfl_down_sync(0xffffffffu, p[tt], o);
            pb[tt] += __shfl_down_sync(0xffffffffu, pb[tt], o);
        }
    }
    #pragma unroll
    for (int o = 16; o > 0; o >>= 1) gv += __shfl_down_sync(0xffffffffu, gv, o);
    if (lane == 0) {
        #pragma unroll
        for (int tt = 0; tt < 9; tt++) { spart[wid][tt] = p[tt]; spartb[wid][tt] = pb[tt]; }
        sgp[wid] = gv;
    }
    __syncthreads();

    if (tid == 64) {
        float s = bg2[0];
        #pragma unroll
        for (int w = 0; w < 8; w++) s += sgp[w];
        g_gate[b] = sigmoidf_(s);
    }
    if (tid == 0) {
        float kkr[9], kkbr[9];
        #pragma unroll
        for (int tt = 0; tt < 9; tt++) {
            float s = bk2[tt], sb = bk2[tt];
            #pragma unroll
            for (int w = 0; w < 8; w++) { s += spart[w][tt]; sb += spartb[w][tt]; }
            kkr[tt] = s; kkbr[tt] = sb;
        }
        int m = sm_flag;
        float v[9];
        #pragma unroll
        for (int i = 0; i < 9; i++) v[i] = m ? kkbr[8 - i] : kkr[i];
        float mx = v[0];
        #pragma unroll
        for (int i = 1; i < 9; i++) mx = fmaxf(mx, v[i]);
        float sum = 0.f;
        #pragma unroll
        for (int i = 0; i < 9; i++) { v[i] = expf(v[i] - mx); sum += v[i]; }
        float inv = 1.f / sum;
        #pragma unroll
        for (int i = 0; i < 9; i++) g_kern[b * 9 + i] = v[i] * inv;
    }
}

// ---------------- M update fused with per-row conv + alpha write -----------
// block (c, b): computes alpha image row c for batch b (conv+blend), writes it,
// then does the M update for memory rows c*32..c*32+31 with fused read_v.
__global__ void mupdate_kernel(const float* __restrict__ M,
                               const float* __restrict__ prev_alpha,
                               const float* __restrict__ bv,
                               float* __restrict__ mnew,
                               float* __restrict__ alpha_out) {
    int b = blockIdx.y;
    int c = blockIdx.x;          // alpha image row / n-chunk
    int d4 = threadIdx.x;        // 0..127
    __shared__ float s_pa[3][34];    // prev_alpha rows c-1..c+1, 1-padded
    __shared__ float sal[NCHUNK];    // computed alpha row
    __shared__ float skk[9];
    __shared__ float sgate;

    // zero halo tile
    if (d4 < 102) (&s_pa[0][0])[d4] = 0.f;
    if (d4 == 102) sgate = g_gate[b];
    if (d4 >= 112 && d4 < 121) skk[d4 - 112] = g_kern[b * 9 + (d4 - 112)];

    // reconstruct erase/add for (b, d4) from KS partials (+bias) — independent
    float4 e = *(const float4*)(bv + d4 * 4);
    float4 v = *(const float4*)(bv + MEM_DIM + d4 * 4);
    #pragma unroll
    for (int ks = 0; ks < KS_EA; ks++) {
        float4 pe = ((const float4*)g_part_ea)[((size_t)ks * BS + b) * 256 + d4];
        float4 pv = ((const float4*)g_part_ea)[((size_t)ks * BS + b) * 256 + 128 + d4];
        e.x += pe.x; e.y += pe.y; e.z += pe.z; e.w += pe.w;
        v.x += pv.x; v.y += pv.y; v.z += pv.z; v.w += pv.w;
    }
    e.x = sigmoidf_(e.x); e.y = sigmoidf_(e.y);
    e.z = sigmoidf_(e.z); e.w = sigmoidf_(e.w);

    // issue the full M read burst NOW — conv math below hides under it
    size_t base = (size_t)b * (NUM_MEM * 128) + (size_t)c * (NCHUNK * 128);
    const float4* Mb = (const float4*)M + base;
    float4* Ob = (float4*)mnew + base;
    float4 m[MBATCH];
    #pragma unroll
    for (int i = 0; i < MBATCH; i++)
        m[i] = __ldcs(&Mb[i * 128 + d4]);

    __syncthreads();  // s_pa zero + skk/sgate visible

    // fill prev_alpha rows c-1..c+1 (zero-padded at image edges)
    if (d4 < 96) {
        int r = d4 >> 5;          // 0..2
        int x = d4 & 31;
        int row = c - 1 + r;
        if (row >= 0 && row < 32)
            s_pa[r][1 + x] = prev_alpha[b * NUM_MEM + row * 32 + x];
    }
    __syncthreads();

    // conv + gated blend for image row c (warp 0)
    if (d4 < 32) {
        float s = 0.f;
        #pragma unroll
        for (int ky = 0; ky < 3; ky++)
            #pragma unroll
            for (int kx = 0; kx < 3; kx++)
                s = fmaf(s_pa[ky][d4 + kx], skk[ky * 3 + kx], s);
        float pa = s_pa[1][1 + d4];
        float g = sgate;
        float aval = s * g + pa * (1.f - g);
        sal[d4] = aval;
        alpha_out[b * NUM_MEM + c * 32 + d4] = aval;
    }
    __syncthreads();

    // compute+store burst with fused read_v partial
    float4 rv = make_float4(0.f, 0.f, 0.f, 0.f);
    #pragma unroll
    for (int i = 0; i < MBATCH; i++) {
        float a = sal[i];
        float4 mn;
        mn.x = fmaf(a, fmaf(-m[i].x, e.x, v.x), m[i].x);
        mn.y = fmaf(a, fmaf(-m[i].y, e.y, v.y), m[i].y);
        mn.z = fmaf(a, fmaf(-m[i].z, e.z, v.z), m[i].z);
        mn.w = fmaf(a, fmaf(-m[i].w, e.w, v.w), m[i].w);
        rv.x = fmaf(a, mn.x, rv.x);
        rv.y = fmaf(a, mn.y, rv.y);
        rv.z = fmaf(a, mn.z, rv.z);
        rv.w = fmaf(a, mn.w, rv.w);
        __stcs(&Ob[i * 128 + d4], mn);
    }
    ((float4*)g_rvpart)[((size_t)c * BS + b) * 128 + d4] = rv;
}

// ---------------- reduce read_v partials (separate kernel: coherent) -------
__global__ void rvreduce_kernel(float* __restrict__ readv) {
    int b = blockIdx.x;
    int d4 = threadIdx.x;  // 128
    float4 s = make_float4(0.f, 0.f, 0.f, 0.f);
    #pragma unroll
    for (int c = 0; c < NSPLIT; c++) {
        float4 p = ((const float4*)g_rvpart)[((size_t)c * BS + b) * 128 + d4];
        s.x += p.x; s.y += p.y; s.z += p.z; s.w += p.w;
    }
    ((float4*)readv)[b * 128 + d4] = s;
}

// ---------------- launch ----------------------------------------------------
extern "C" void kernel_launch(void* const* d_in, const int* in_sizes, int n_in,
                              void* d_out, int out_size) {
    const float* h          = (const float*)d_in[0];
    const float* a          = (const float*)d_in[1];
    const float* prev_alpha = (const float*)d_in[3];
    const float* M          = (const float*)d_in[4];
    const float* Wv         = (const float*)d_in[5];
    const float* bv         = (const float*)d_in[6];
    const float* Wk1        = (const float*)d_in[7];
    const float* bk1        = (const float*)d_in[8];
    const float* Wk2        = (const float*)d_in[9];
    const float* bk2        = (const float*)d_in[10];
    const float* Wg1        = (const float*)d_in[11];
    const float* bg1        = (const float*)d_in[12];
    const float* Wg2        = (const float*)d_in[13];
    const float* bg2        = (const float*)d_in[14];

    float* out = (float*)d_out;
    float* out_readv = out + OUT_READV;
    float* out_other = out + OUT_OTHER;
    float* out_mnew  = out + OUT_MNEW;
    float* out_alpha = out + OUT_ALPHA;

    static cudaStream_t s1 = 0;
    static cudaEvent_t evFork = 0, evJoin = 0, evJoin2 = 0;
    static float *p_ea = 0, *p_g1 = 0, *p_ot = 0;
    static int tried = 0, ok = 0;
    if (!tried) {
        tried = 1;
        ok = (cudaStreamCreateWithFlags(&s1, cudaStreamNonBlocking) == cudaSuccess) &&
             (cudaEventCreateWithFlags(&evFork, cudaEventDisableTiming) == cudaSuccess) &&
             (cudaEventCreateWithFlags(&evJoin, cudaEventDisableTiming) == cudaSuccess) &&
             (cudaEventCreateWithFlags(&evJoin2, cudaEventDisableTiming) == cudaSuccess) &&
             (cudaGetSymbolAddress((void**)&p_ea, g_part_ea) == cudaSuccess) &&
             (cudaGetSymbolAddress((void**)&p_g1, g_part_g1) == cudaSuccess) &&
             (cudaGetSymbolAddress((void**)&p_ot, g_part_ot) == cudaSuccess);
    }
    if (!ok) return;

    // fork
    cudaEventRecord(evFork, 0);
    cudaStreamWaitEvent(s1, evFork, 0);

    // s1: erase/add slab partials (Wv cols 0..1024), KS=2 -> 128 blocks
    gemm_part_kernel<<<dim3(16, 4, KS_EA), 256, 0, s1>>>(
        h, Wv, 3 * MEM_DIM, 0, p_ea, 2 * MEM_DIM, HID / KS_EA);
    cudaEventRecord(evJoin, s1);
    // s1: other_v slab (overlaps mupdate)
    gemm_part_kernel<<<dim3(8, 4, KS_OT), 256, 0, s1>>>(
        h, Wv, 3 * MEM_DIM, 2 * MEM_DIM, p_ot, MEM_DIM, HID / KS_OT);
    epi_other_kernel<<<128, 256, 0, s1>>>(bv, out_other);
    cudaEventRecord(evJoin2, s1);

    // default: g1 gemm partials (KS=4) -> prep (kernelnet+gate) -> mupdate
    gemm_part_kernel<<<dim3(8, 4, KS_G1), 256>>>(
        h, Wg1, MEM_DIM, 0, p_g1, MEM_DIM, HID / KS_G1);
    prep_kernel<<<BS, 256>>>(a, Wk1, bk1, Wk2, bk2, bg1, Wg2, bg2);

    cudaStreamWaitEvent(0, evJoin, 0);
    mupdate_kernel<<<dim3(NSPLIT, BS), 128>>>(M, prev_alpha, bv, out_mnew, out_alpha);
    rvreduce_kernel<<<BS, 128>>>(out_readv);
    cudaStreamWaitEvent(0, evJoin2, 0);
}